// round 11
// baseline (speedup 1.0000x reference)
#include <cuda_runtime.h>
#include <cuda_fp16.h>
#include <cstdint>

#define BATCH 256
#define ISZ   512
#define STEPS 256
#define HID   512
#define GH    1536
#define NCTA  128
#define MROWS (STEPS * BATCH)     // 65536

// ---------------- scratch ----------------
__device__ __half g_x16[(size_t)MROWS * ISZ];
__device__ __half g_w16[(size_t)GH * ISZ];
__device__ float g_gi[(size_t)MROWS * GH];
__device__ __half g_h16[2][BATCH * HID];
__device__ __align__(128) unsigned g_flags[4][32];   // one 128B line per batch group

// ---------------- helpers ----------------
__device__ __forceinline__ uint32_t smem_to_u32(const void* p) {
    uint32_t a;
    asm("{ .reg .u64 t; cvta.to.shared.u64 t, %1; cvt.u32.u64 %0, t; }" : "=r"(a) : "l"(p));
    return a;
}
__device__ __forceinline__ void cp16(uint32_t dst, const void* src) {
    asm volatile("cp.async.cg.shared.global [%0], [%1], 16;" :: "r"(dst), "l"(src));
}
#define CP_COMMIT() asm volatile("cp.async.commit_group;" ::: "memory")
#define CP_WAIT(n)  asm volatile("cp.async.wait_group %0;" :: "n"(n) : "memory")

__device__ __forceinline__ void ldsm_x4(uint32_t addr, uint32_t r[4]) {
    asm volatile("ldmatrix.sync.aligned.m8n8.x4.shared.b16 {%0,%1,%2,%3}, [%4];"
                 : "=r"(r[0]), "=r"(r[1]), "=r"(r[2]), "=r"(r[3]) : "r"(addr));
}
__device__ __forceinline__ void ldsm_x2(uint32_t addr, uint32_t r[2]) {
    asm volatile("ldmatrix.sync.aligned.m8n8.x2.shared.b16 {%0,%1}, [%2];"
                 : "=r"(r[0]), "=r"(r[1]) : "r"(addr));
}
__device__ __forceinline__ void mma_f16(float d[4], const uint32_t a[4], const uint32_t b[2]) {
    asm volatile("mma.sync.aligned.m16n8k16.row.col.f32.f16.f16.f32 "
                 "{%0,%1,%2,%3}, {%4,%5,%6,%7}, {%8,%9}, {%0,%1,%2,%3};"
                 : "+f"(d[0]), "+f"(d[1]), "+f"(d[2]), "+f"(d[3])
                 : "r"(a[0]), "r"(a[1]), "r"(a[2]), "r"(a[3]), "r"(b[0]), "r"(b[1]));
}
__device__ __forceinline__ float fast_sigmoid(float v) {
    return __fdividef(1.f, 1.f + __expf(-v));
}
__device__ __forceinline__ float fast_tanh(float v) {
    float e = __expf(-2.f * v);
    return __fdividef(1.f - e, 1.f + e);
}

// ---------------- Wih -> fp16 ----------------
__global__ void k_w_convert(const float* __restrict__ wih) {
    size_t i = (size_t)blockIdx.x * 1024 + threadIdx.x * 4;
    #pragma unroll
    for (int j = 0; j < 4; ++j)
        g_w16[i + j] = __float2half_rn(wih[i + j]);
}

// ---------------- x [B][I][S] -> g_x16 [(s*B+b)][i] fp16 ----------------
__global__ void k_x_transpose(const float* __restrict__ x) {
    __shared__ float tile[32][33];
    int s0 = blockIdx.x * 32;
    int i0 = blockIdx.y * 32;
    int b  = blockIdx.z;
    int tx = threadIdx.x, ty = threadIdx.y;
    #pragma unroll
    for (int j = 0; j < 4; ++j)
        tile[ty + 8 * j][tx] = x[((size_t)b * ISZ + i0 + ty + 8 * j) * STEPS + s0 + tx];
    __syncthreads();
    #pragma unroll
    for (int j = 0; j < 4; ++j) {
        int s = s0 + ty + 8 * j;
        float v = tile[tx][ty + 8 * j];
        g_x16[((size_t)s * BATCH + b) * ISZ + i0 + tx] = __float2half_rn(v);
    }
}

// ---------------- HMMA GEMM: gi = x(fp16) @ Wih(fp16)^T + bias_ih ----------------
#define SA 72
#define ATILE_B (128 * SA * 2)
#define GEMM_SMEM (2 * 2 * ATILE_B)

__device__ __forceinline__ void gi_issue_load(uint32_t sb, int tid, int m0, int n0,
                                              int chunk, int buf) {
    const int k0 = chunk * 64;
    const __half* srcs[2] = {g_x16, g_w16};
    const int rowbase[2] = {m0, n0};
    #pragma unroll
    for (int t = 0; t < 2; ++t) {
        const __half* src = srcs[t];
        uint32_t dst0 = sb + buf * 2 * ATILE_B + t * ATILE_B;
        #pragma unroll
        for (int i = 0; i < 4; ++i) {
            int lin = tid + 256 * i;
            int row = lin >> 3;
            int cq  = lin & 7;
            cp16(dst0 + row * (SA * 2) + cq * 16,
                 src + (size_t)(rowbase[t] + row) * ISZ + k0 + cq * 8);
        }
    }
}

__global__ void __launch_bounds__(256) k_gemm_gi(const float* __restrict__ bias_ih) {
    extern __shared__ char smem[];
    uint32_t sb = smem_to_u32(smem);
    const int tid = threadIdx.x;
    const int lane = tid & 31;
    const int wid = tid >> 5;
    const int wm = wid & 3;
    const int wn = wid >> 2;
    const int m0 = blockIdx.y * 128;
    const int n0 = blockIdx.x * 128;

    const int t4 = lane >> 3;
    const int arow = (t4 & 1) * 8 + (lane & 7);
    const int acol = (t4 >> 1) * 8;
    const int brow = (t4 >> 1) * 8 + (lane & 7);
    const int bcol = (t4 & 1) * 8;

    float acc[2][8][4];
    #pragma unroll
    for (int i = 0; i < 2; ++i)
        #pragma unroll
        for (int j = 0; j < 8; ++j)
            #pragma unroll
            for (int v = 0; v < 4; ++v) acc[i][j][v] = 0.f;

    gi_issue_load(sb, tid, m0, n0, 0, 0);
    CP_COMMIT();

    for (int c = 0; c < 8; ++c) {
        if (c < 7) {
            gi_issue_load(sb, tid, m0, n0, c + 1, (c + 1) & 1);
            CP_COMMIT();
            CP_WAIT(1);
        } else {
            CP_WAIT(0);
        }
        __syncthreads();
        const int buf = c & 1;
        const uint32_t bufb = sb + buf * 2 * ATILE_B;

        #pragma unroll
        for (int kk = 0; kk < 64; kk += 16) {
            uint32_t Ax[2][4], Bx[8][2];
            #pragma unroll
            for (int mt = 0; mt < 2; ++mt) {
                uint32_t r = (wm * 32 + mt * 16 + arow) * (SA * 2) + (kk + acol) * 2;
                ldsm_x4(bufb + 0 * ATILE_B + r, Ax[mt]);
            }
            #pragma unroll
            for (int pt = 0; pt < 4; ++pt) {
                uint32_t r = (wn * 64 + pt * 16 + brow) * (SA * 2) + (kk + bcol) * 2;
                uint32_t q[4];
                ldsm_x4(bufb + 1 * ATILE_B + r, q);
                Bx[2 * pt][0] = q[0]; Bx[2 * pt][1] = q[1];
                Bx[2 * pt + 1][0] = q[2]; Bx[2 * pt + 1][1] = q[3];
            }
            #pragma unroll
            for (int mt = 0; mt < 2; ++mt)
                #pragma unroll
                for (int nt = 0; nt < 8; ++nt)
                    mma_f16(acc[mt][nt], Ax[mt], Bx[nt]);
        }
        __syncthreads();
    }

    #pragma unroll
    for (int nt = 0; nt < 8; ++nt) {
        int n_base = n0 + wn * 64 + nt * 8 + (lane & 3) * 2;
        float2 bb = *(const float2*)(bias_ih + n_base);
        #pragma unroll
        for (int mt = 0; mt < 2; ++mt) {
            int m_base = m0 + wm * 32 + mt * 16 + (lane >> 2);
            float2 v0, v1;
            v0.x = acc[mt][nt][0] + bb.x;
            v0.y = acc[mt][nt][1] + bb.y;
            v1.x = acc[mt][nt][2] + bb.x;
            v1.y = acc[mt][nt][3] + bb.y;
            *(float2*)(g_gi + (size_t)m_base * GH + n_base) = v0;
            *(float2*)(g_gi + (size_t)(m_base + 8) * GH + n_base) = v1;
        }
    }
}

// ---------------- persistent GRU recurrence v9: R9 structure + flag barrier --------
// 128 CTAs = 4 batch-groups (64 rows) x 32 col-groups (16 cols x 3 gates = 48 N-rows).
// Barrier: 32 distinct flag words per bg (one 128B line); store-release arrival,
// 32-thread parallel acquire-poll (one coalesced L2 access per poll round).
__device__ __forceinline__ void flagbar(int bg, int cg, unsigned target) {
    __syncthreads();
    if (threadIdx.x == 0) {
        asm volatile("st.global.release.gpu.u32 [%0], %1;"
                     :: "l"(&g_flags[bg][cg]), "r"(target) : "memory");
    }
    if (threadIdx.x < 32) {
        const unsigned* f = &g_flags[bg][threadIdx.x];
        unsigned v;
        do {
            asm volatile("ld.global.acquire.gpu.u32 %0, [%1];"
                         : "=r"(v) : "l"(f) : "memory");
        } while ((int)(v - target) < 0);
    }
    __syncthreads();
}

#define A_OFF 0
#define B_OFF 65536                      // A: 64 rows x 1024 B
#define BSTR 520
#define GH_OFF (B_OFF + 48 * BSTR * 2)   // 115456 (separate gh region)
#define GH_STR 50
#define REC2_SMEM (GH_OFF + 64 * GH_STR * 4)   // 128256

__device__ __forceinline__ uint32_t a_off(int row, int kb) {
    uint32_t u = ((uint32_t)kb >> 3) ^ (row & 7);
    return (uint32_t)row * 1024 + u * 16;
}

__global__ void __launch_bounds__(256, 1) k_gru_recur(
    const float* __restrict__ whh, const float* __restrict__ bhh,
    float* __restrict__ out)
{
    extern __shared__ char smem[];
    uint32_t sb = smem_to_u32(smem);
    float* gh = (float*)(smem + GH_OFF);

    const int cta = blockIdx.x;
    const int cg  = cta & 31;
    const int bg0 = cta >> 5;
    const int tid = threadIdx.x;
    const int lane = tid & 31;
    const int wid = tid >> 5;
    const int wm = wid & 3;
    const int wn = wid >> 2;

    const int t4 = lane >> 3;
    const int arow = (t4 & 1) * 8 + (lane & 7);
    const int acol = (t4 >> 1) * 8;
    const int brow = (t4 >> 1) * 8 + (lane & 7);
    const int bcol = (t4 & 1) * 8;
    const int brow2 = lane & 7;
    const int bcol2 = ((lane >> 3) & 1) * 8;

    // resident Whh slice -> fp16 (single)
    for (int idx = tid; idx < 48 * 128; idx += 256) {
        int r = idx >> 7;
        int kq = idx & 127;
        int g = r >> 4, c = r & 15;
        float4 v = *(const float4*)(whh + (size_t)(g * HID + cg * 16 + c) * HID + kq * 4);
        __half h4[4];
        h4[0] = __float2half_rn(v.x);
        h4[1] = __float2half_rn(v.y);
        h4[2] = __float2half_rn(v.z);
        h4[3] = __float2half_rn(v.w);
        *(uint2*)(smem + B_OFF + r * (BSTR * 2) + kq * 8) = *(uint2*)h4;
    }

    const int gb = tid >> 2;
    const int cq = tid & 3;
    const int c0 = cq * 4;
    const int gcol0 = cg * 16 + c0;
    float br[4], bz[4], bn[4];
    #pragma unroll
    for (int i = 0; i < 4; ++i) {
        br[i] = bhh[gcol0 + i];
        bz[i] = bhh[HID + gcol0 + i];
        bn[i] = bhh[2 * HID + gcol0 + i];
    }

    {   // zero h fp16 buffer 0
        uint2 z = make_uint2(0, 0);
        *(uint2*)((char*)g_h16[0] + ((size_t)cta * 256 + tid) * 8) = z;
    }
    float h_old[4] = {0.f, 0.f, 0.f, 0.f};

    // base generation from own flag (identical history across the bg's CTAs)
    unsigned base;
    asm volatile("ld.global.acquire.gpu.u32 %0, [%1];"
                 : "=r"(base) : "l"(&g_flags[bg0][cg]) : "memory");
    flagbar(bg0, cg, base + 1);

    const uint32_t bof = sb + B_OFF;
    const int nb = wn * 24;
    const int bglob = bg0 * 64 + gb;

    for (int s = 0; s < STEPS; ++s) {
        const int cur = s & 1, nxt = cur ^ 1;
        const __half* hsrc = g_h16[cur];

        // issue all 4 A chunks
        #pragma unroll
        for (int pre = 0; pre < 4; ++pre) {
            #pragma unroll
            for (int i = 0; i < 4; ++i) {
                int lin = tid + 256 * i;
                int row = lin >> 4;
                int kb = pre * 128 + (lin & 15) * 8;
                cp16(sb + A_OFF + a_off(row, kb),
                     hsrc + (size_t)(bg0 * 64 + row) * HID + kb);
            }
            CP_COMMIT();
        }

        const float* gip = g_gi + ((size_t)s * BATCH + bglob) * GH;
        float4 gr4 = __ldcg((const float4*)(gip + gcol0));
        float4 gz4 = __ldcg((const float4*)(gip + HID + gcol0));
        float4 gn4 = __ldcg((const float4*)(gip + 2 * HID + gcol0));

        float acc[3][4];
        #pragma unroll
        for (int j = 0; j < 3; ++j)
            #pragma unroll
            for (int v = 0; v < 4; ++v) acc[j][v] = 0.f;

        #pragma unroll
        for (int kc = 0; kc < 4; ++kc) {
            if (kc == 0)      CP_WAIT(3);
            else if (kc == 1) CP_WAIT(2);
            else if (kc == 2) CP_WAIT(1);
            else              CP_WAIT(0);
            __syncthreads();

            #pragma unroll
            for (int t = 0; t < 8; ++t) {
                const int kk = kc * 128 + t * 16;
                uint32_t Ax[4], Bx[3][2];
                {
                    int rr = wm * 16 + arow;
                    ldsm_x4(sb + A_OFF + a_off(rr, kk + acol), Ax);
                }
                {
                    uint32_t q[4];
                    uint32_t r16 = (nb + brow) * (BSTR * 2) + (kk + bcol) * 2;
                    ldsm_x4(bof + r16, q);
                    Bx[0][0] = q[0]; Bx[0][1] = q[1];
                    Bx[1][0] = q[2]; Bx[1][1] = q[3];
                    uint32_t r8 = (nb + 16 + brow2) * (BSTR * 2) + (kk + bcol2) * 2;
                    ldsm_x2(bof + r8, Bx[2]);
                }
                #pragma unroll
                for (int nt = 0; nt < 3; ++nt)
                    mma_f16(acc[nt], Ax, Bx[nt]);
            }
        }

        // gh lives in its own region: no sync needed before writing own fragments
        {
            int row0 = wm * 16 + (lane >> 2);
            int col0 = nb + (lane & 3) * 2;
            #pragma unroll
            for (int nt = 0; nt < 3; ++nt) {
                *(float2*)(gh + row0 * GH_STR + col0 + nt * 8) = make_float2(acc[nt][0], acc[nt][1]);
                *(float2*)(gh + (row0 + 8) * GH_STR + col0 + nt * 8) = make_float2(acc[nt][2], acc[nt][3]);
            }
        }
        __syncthreads();

        {
            float grv[4] = {gr4.x, gr4.y, gr4.z, gr4.w};
            float gzv[4] = {gz4.x, gz4.y, gz4.z, gz4.w};
            float gnv[4] = {gn4.x, gn4.y, gn4.z, gn4.w};
            __half h16v[4];
            float hnew4[4];
            #pragma unroll
            for (int i = 0; i < 4; ++i) {
                int c = c0 + i;
                float ar = gh[gb * GH_STR + 0 * 16 + c];
                float az = gh[gb * GH_STR + 1 * 16 + c];
                float an = gh[gb * GH_STR + 2 * 16 + c];
                float rg = fast_sigmoid(grv[i] + ar + br[i]);
                float zg = fast_sigmoid(gzv[i] + az + bz[i]);
                float ng = fast_tanh(gnv[i] + rg * (an + bn[i]));
                float hnew = (1.f - zg) * ng + zg * h_old[i];
                h_old[i] = hnew;               // exact fp32 state in registers
                hnew4[i] = hnew;
                h16v[i] = __float2half_rn(hnew);
            }
            size_t ho = (size_t)bglob * HID + gcol0;
            *(uint2*)(g_h16[nxt] + ho) = *(uint2*)h16v;
            if (s == STEPS - 1)
                *(float4*)(out + ho) = *(float4*)hnew4;
        }

        flagbar(bg0, cg, base + 2 + s);
    }
}

// ---------------- launcher ----------------
extern "C" void kernel_launch(void* const* d_in, const int* in_sizes, int n_in,
                              void* d_out, int out_size) {
    const float* x   = (const float*)d_in[0];
    const float* wih = (const float*)d_in[1];
    const float* whh = (const float*)d_in[2];
    const float* bih = (const float*)d_in[3];
    const float* bhh = (const float*)d_in[4];
    float* out = (float*)d_out;

    cudaFuncSetAttribute(k_gru_recur, cudaFuncAttributeMaxDynamicSharedMemorySize,
                         REC2_SMEM);
    cudaFuncSetAttribute(k_gemm_gi, cudaFuncAttributeMaxDynamicSharedMemorySize,
                         GEMM_SMEM);

    k_w_convert<<<(GH * ISZ) / 1024, 256>>>(wih);
    k_x_transpose<<<dim3(STEPS / 32, ISZ / 32, BATCH), dim3(32, 8)>>>(x);
    k_gemm_gi<<<dim3(GH / 128, MROWS / 128), 256, GEMM_SMEM>>>(bih);
    k_gru_recur<<<NCTA, 256, REC2_SMEM>>>(whh, bhh, out);
}

// round 12
// speedup vs baseline: 2.1754x; 2.1754x over previous
#include <cuda_runtime.h>
#include <cuda_fp16.h>
#include <cstdint>

#define BATCH 256
#define ISZ   512
#define STEPS 256
#define HID   512
#define GH    1536
#define NCTA  128
#define MROWS (STEPS * BATCH)     // 65536

// ---------------- scratch ----------------
__device__ __half g_x16[(size_t)MROWS * ISZ];
__device__ __half g_w16[(size_t)GH * ISZ];
__device__ __half g_gih[(size_t)MROWS * GH];     // gi in fp16 (no bias)
__device__ __half g_h16[2][BATCH * HID];
__device__ unsigned g_bg_cnt[4];                 // zeroed each replay by k_w_convert

// ---------------- helpers ----------------
__device__ __forceinline__ uint32_t smem_to_u32(const void* p) {
    uint32_t a;
    asm("{ .reg .u64 t; cvta.to.shared.u64 t, %1; cvt.u32.u64 %0, t; }" : "=r"(a) : "l"(p));
    return a;
}
__device__ __forceinline__ void cp16(uint32_t dst, const void* src) {
    asm volatile("cp.async.cg.shared.global [%0], [%1], 16;" :: "r"(dst), "l"(src));
}
#define CP_COMMIT() asm volatile("cp.async.commit_group;" ::: "memory")
#define CP_WAIT(n)  asm volatile("cp.async.wait_group %0;" :: "n"(n) : "memory")

__device__ __forceinline__ void ldsm_x4(uint32_t addr, uint32_t r[4]) {
    asm volatile("ldmatrix.sync.aligned.m8n8.x4.shared.b16 {%0,%1,%2,%3}, [%4];"
                 : "=r"(r[0]), "=r"(r[1]), "=r"(r[2]), "=r"(r[3]) : "r"(addr));
}
__device__ __forceinline__ void ldsm_x2(uint32_t addr, uint32_t r[2]) {
    asm volatile("ldmatrix.sync.aligned.m8n8.x2.shared.b16 {%0,%1}, [%2];"
                 : "=r"(r[0]), "=r"(r[1]) : "r"(addr));
}
__device__ __forceinline__ void mma_f16(float d[4], const uint32_t a[4], const uint32_t b[2]) {
    asm volatile("mma.sync.aligned.m16n8k16.row.col.f32.f16.f16.f32 "
                 "{%0,%1,%2,%3}, {%4,%5,%6,%7}, {%8,%9}, {%0,%1,%2,%3};"
                 : "+f"(d[0]), "+f"(d[1]), "+f"(d[2]), "+f"(d[3])
                 : "r"(a[0]), "r"(a[1]), "r"(a[2]), "r"(a[3]), "r"(b[0]), "r"(b[1]));
}
__device__ __forceinline__ float fast_sigmoid(float v) {
    return __fdividef(1.f, 1.f + __expf(-v));
}
__device__ __forceinline__ float fast_tanh(float v) {
    float e = __expf(-2.f * v);
    return __fdividef(1.f - e, 1.f + e);
}

// ---------------- Wih -> fp16 + barrier counter reset ----------------
__global__ void k_w_convert(const float* __restrict__ wih) {
    if (blockIdx.x == 0 && threadIdx.x < 4)
        g_bg_cnt[threadIdx.x] = 0;                 // stream-ordered before recurrence
    size_t i = (size_t)blockIdx.x * 1024 + threadIdx.x * 4;
    #pragma unroll
    for (int j = 0; j < 4; ++j)
        g_w16[i + j] = __float2half_rn(wih[i + j]);
}

// ---------------- x [B][I][S] -> g_x16 [(s*B+b)][i] fp16 ----------------
__global__ void k_x_transpose(const float* __restrict__ x) {
    __shared__ float tile[32][33];
    int s0 = blockIdx.x * 32;
    int i0 = blockIdx.y * 32;
    int b  = blockIdx.z;
    int tx = threadIdx.x, ty = threadIdx.y;
    #pragma unroll
    for (int j = 0; j < 4; ++j)
        tile[ty + 8 * j][tx] = x[((size_t)b * ISZ + i0 + ty + 8 * j) * STEPS + s0 + tx];
    __syncthreads();
    #pragma unroll
    for (int j = 0; j < 4; ++j) {
        int s = s0 + ty + 8 * j;
        float v = tile[tx][ty + 8 * j];
        g_x16[((size_t)s * BATCH + b) * ISZ + i0 + tx] = __float2half_rn(v);
    }
}

// ---------------- HMMA GEMM: gi = x(fp16) @ Wih(fp16)^T  (fp16 out, no bias) -------
#define SA 72
#define ATILE_B (128 * SA * 2)
#define GEMM_SMEM (2 * 2 * ATILE_B)

__device__ __forceinline__ void gi_issue_load(uint32_t sb, int tid, int m0, int n0,
                                              int chunk, int buf) {
    const int k0 = chunk * 64;
    const __half* srcs[2] = {g_x16, g_w16};
    const int rowbase[2] = {m0, n0};
    #pragma unroll
    for (int t = 0; t < 2; ++t) {
        const __half* src = srcs[t];
        uint32_t dst0 = sb + buf * 2 * ATILE_B + t * ATILE_B;
        #pragma unroll
        for (int i = 0; i < 4; ++i) {
            int lin = tid + 256 * i;
            int row = lin >> 3;
            int cq  = lin & 7;
            cp16(dst0 + row * (SA * 2) + cq * 16,
                 src + (size_t)(rowbase[t] + row) * ISZ + k0 + cq * 8);
        }
    }
}

__global__ void __launch_bounds__(256) k_gemm_gi() {
    extern __shared__ char smem[];
    uint32_t sb = smem_to_u32(smem);
    const int tid = threadIdx.x;
    const int lane = tid & 31;
    const int wid = tid >> 5;
    const int wm = wid & 3;
    const int wn = wid >> 2;
    const int m0 = blockIdx.y * 128;
    const int n0 = blockIdx.x * 128;

    const int t4 = lane >> 3;
    const int arow = (t4 & 1) * 8 + (lane & 7);
    const int acol = (t4 >> 1) * 8;
    const int brow = (t4 >> 1) * 8 + (lane & 7);
    const int bcol = (t4 & 1) * 8;

    float acc[2][8][4];
    #pragma unroll
    for (int i = 0; i < 2; ++i)
        #pragma unroll
        for (int j = 0; j < 8; ++j)
            #pragma unroll
            for (int v = 0; v < 4; ++v) acc[i][j][v] = 0.f;

    gi_issue_load(sb, tid, m0, n0, 0, 0);
    CP_COMMIT();

    for (int c = 0; c < 8; ++c) {
        if (c < 7) {
            gi_issue_load(sb, tid, m0, n0, c + 1, (c + 1) & 1);
            CP_COMMIT();
            CP_WAIT(1);
        } else {
            CP_WAIT(0);
        }
        __syncthreads();
        const int buf = c & 1;
        const uint32_t bufb = sb + buf * 2 * ATILE_B;

        #pragma unroll
        for (int kk = 0; kk < 64; kk += 16) {
            uint32_t Ax[2][4], Bx[8][2];
            #pragma unroll
            for (int mt = 0; mt < 2; ++mt) {
                uint32_t r = (wm * 32 + mt * 16 + arow) * (SA * 2) + (kk + acol) * 2;
                ldsm_x4(bufb + 0 * ATILE_B + r, Ax[mt]);
            }
            #pragma unroll
            for (int pt = 0; pt < 4; ++pt) {
                uint32_t r = (wn * 64 + pt * 16 + brow) * (SA * 2) + (kk + bcol) * 2;
                uint32_t q[4];
                ldsm_x4(bufb + 1 * ATILE_B + r, q);
                Bx[2 * pt][0] = q[0]; Bx[2 * pt][1] = q[1];
                Bx[2 * pt + 1][0] = q[2]; Bx[2 * pt + 1][1] = q[3];
            }
            #pragma unroll
            for (int mt = 0; mt < 2; ++mt)
                #pragma unroll
                for (int nt = 0; nt < 8; ++nt)
                    mma_f16(acc[mt][nt], Ax[mt], Bx[nt]);
        }
        __syncthreads();
    }

    // epilogue: store raw fp16 (bias folded into recurrence gate constants)
    #pragma unroll
    for (int nt = 0; nt < 8; ++nt) {
        int n_base = n0 + wn * 64 + nt * 8 + (lane & 3) * 2;
        #pragma unroll
        for (int mt = 0; mt < 2; ++mt) {
            int m_base = m0 + wm * 32 + mt * 16 + (lane >> 2);
            __half2 v0 = __floats2half2_rn(acc[mt][nt][0], acc[mt][nt][1]);
            __half2 v1 = __floats2half2_rn(acc[mt][nt][2], acc[mt][nt][3]);
            *(__half2*)(g_gih + (size_t)m_base * GH + n_base) = v0;
            *(__half2*)(g_gih + (size_t)(m_base + 8) * GH + n_base) = v1;
        }
    }
}

// ---------------- persistent GRU recurrence v10: R9 structure + REDG barrier -------
// 128 CTAs = 4 batch-groups (64 rows) x 32 col-groups (16 cols x 3 gates = 48 N-rows).
// Barrier: monotonic per-bg counter (zeroed each replay); arrival = red.release.add
// (no return trip), 1 poller/CTA on the counter word. Target k-th barrier = 32*k.
__device__ __forceinline__ void cntbar(int bg, unsigned target) {
    __syncthreads();
    if (threadIdx.x == 0) {
        asm volatile("red.release.gpu.global.add.u32 [%0], %1;"
                     :: "l"(&g_bg_cnt[bg]), "r"(1u) : "memory");
        unsigned v;
        do {
            asm volatile("ld.global.acquire.gpu.u32 %0, [%1];"
                         : "=r"(v) : "l"(&g_bg_cnt[bg]) : "memory");
        } while (v < target);
    }
    __syncthreads();
}

#define A_OFF 0
#define B_OFF 65536                      // A: 64 rows x 1024 B
#define BSTR 520
#define GH_OFF (B_OFF + 48 * BSTR * 2)   // 115456 (separate gh region)
#define GH_STR 50
#define REC2_SMEM (GH_OFF + 64 * GH_STR * 4)   // 128256

__device__ __forceinline__ uint32_t a_off(int row, int kb) {
    uint32_t u = ((uint32_t)kb >> 3) ^ (row & 7);
    return (uint32_t)row * 1024 + u * 16;
}

__global__ void __launch_bounds__(256, 1) k_gru_recur(
    const float* __restrict__ whh, const float* __restrict__ bih,
    const float* __restrict__ bhh, float* __restrict__ out)
{
    extern __shared__ char smem[];
    uint32_t sb = smem_to_u32(smem);
    float* gh = (float*)(smem + GH_OFF);

    const int cta = blockIdx.x;
    const int cg  = cta & 31;
    const int bg0 = cta >> 5;
    const int tid = threadIdx.x;
    const int lane = tid & 31;
    const int wid = tid >> 5;
    const int wm = wid & 3;
    const int wn = wid >> 2;

    const int t4 = lane >> 3;
    const int arow = (t4 & 1) * 8 + (lane & 7);
    const int acol = (t4 >> 1) * 8;
    const int brow = (t4 >> 1) * 8 + (lane & 7);
    const int bcol = (t4 & 1) * 8;
    const int brow2 = lane & 7;
    const int bcol2 = ((lane >> 3) & 1) * 8;

    // resident Whh slice -> fp16
    for (int idx = tid; idx < 48 * 128; idx += 256) {
        int r = idx >> 7;
        int kq = idx & 127;
        int g = r >> 4, c = r & 15;
        float4 v = *(const float4*)(whh + (size_t)(g * HID + cg * 16 + c) * HID + kq * 4);
        __half h4[4];
        h4[0] = __float2half_rn(v.x);
        h4[1] = __float2half_rn(v.y);
        h4[2] = __float2half_rn(v.z);
        h4[3] = __float2half_rn(v.w);
        *(uint2*)(smem + B_OFF + r * (BSTR * 2) + kq * 8) = *(uint2*)h4;
    }

    const int gb = tid >> 2;
    const int cq = tid & 3;
    const int c0 = cq * 4;
    const int gcol0 = cg * 16 + c0;
    // folded gate biases: r,z fold bih+bhh; n keeps them separate (r multiplies bhh_n)
    float brt[4], bzt[4], bni[4], bnh[4];
    #pragma unroll
    for (int i = 0; i < 4; ++i) {
        brt[i] = bih[gcol0 + i] + bhh[gcol0 + i];
        bzt[i] = bih[HID + gcol0 + i] + bhh[HID + gcol0 + i];
        bni[i] = bih[2 * HID + gcol0 + i];
        bnh[i] = bhh[2 * HID + gcol0 + i];
    }

    {   // zero h fp16 buffer 0 (disjoint 8B chunks)
        uint2 z = make_uint2(0, 0);
        *(uint2*)((char*)g_h16[0] + ((size_t)cta * 256 + tid) * 8) = z;
    }
    float h_old[4] = {0.f, 0.f, 0.f, 0.f};

    cntbar(bg0, 32u);           // startup barrier (counter pre-zeroed this replay)

    const uint32_t bof = sb + B_OFF;
    const int nb = wn * 24;
    const int bglob = bg0 * 64 + gb;

    for (int s = 0; s < STEPS; ++s) {
        const int cur = s & 1, nxt = cur ^ 1;
        const __half* hsrc = g_h16[cur];

        // issue all 4 A chunks (deep pipeline)
        #pragma unroll
        for (int pre = 0; pre < 4; ++pre) {
            #pragma unroll
            for (int i = 0; i < 4; ++i) {
                int lin = tid + 256 * i;
                int row = lin >> 4;
                int kb = pre * 128 + (lin & 15) * 8;
                cp16(sb + A_OFF + a_off(row, kb),
                     hsrc + (size_t)(bg0 * 64 + row) * HID + kb);
            }
            CP_COMMIT();
        }

        // gi prefetch (fp16, 4 cols per gate)
        const __half* gip = g_gih + ((size_t)s * BATCH + bglob) * GH;
        uint2 gru = __ldcg((const uint2*)(gip + gcol0));
        uint2 gzu = __ldcg((const uint2*)(gip + HID + gcol0));
        uint2 gnu = __ldcg((const uint2*)(gip + 2 * HID + gcol0));

        float acc[3][4];
        #pragma unroll
        for (int j = 0; j < 3; ++j)
            #pragma unroll
            for (int v = 0; v < 4; ++v) acc[j][v] = 0.f;

        #pragma unroll
        for (int kc = 0; kc < 4; ++kc) {
            if (kc == 0)      CP_WAIT(3);
            else if (kc == 1) CP_WAIT(2);
            else if (kc == 2) CP_WAIT(1);
            else              CP_WAIT(0);
            __syncthreads();

            #pragma unroll
            for (int t = 0; t < 8; ++t) {
                const int kk = kc * 128 + t * 16;
                uint32_t Ax[4], Bx[3][2];
                {
                    int rr = wm * 16 + arow;
                    ldsm_x4(sb + A_OFF + a_off(rr, kk + acol), Ax);
                }
                {
                    uint32_t q[4];
                    uint32_t r16 = (nb + brow) * (BSTR * 2) + (kk + bcol) * 2;
                    ldsm_x4(bof + r16, q);
                    Bx[0][0] = q[0]; Bx[0][1] = q[1];
                    Bx[1][0] = q[2]; Bx[1][1] = q[3];
                    uint32_t r8 = (nb + 16 + brow2) * (BSTR * 2) + (kk + bcol2) * 2;
                    ldsm_x2(bof + r8, Bx[2]);
                }
                #pragma unroll
                for (int nt = 0; nt < 3; ++nt)
                    mma_f16(acc[nt], Ax, Bx[nt]);
            }
        }

        // write gh fragments (own region; no pre-sync needed)
        {
            int row0 = wm * 16 + (lane >> 2);
            int col0 = nb + (lane & 3) * 2;
            #pragma unroll
            for (int nt = 0; nt < 3; ++nt) {
                *(float2*)(gh + row0 * GH_STR + col0 + nt * 8) = make_float2(acc[nt][0], acc[nt][1]);
                *(float2*)(gh + (row0 + 8) * GH_STR + col0 + nt * 8) = make_float2(acc[nt][2], acc[nt][3]);
            }
        }
        __syncthreads();

        {
            __half2 grh = *(__half2*)&gru.x, grh2 = *(__half2*)&gru.y;
            __half2 gzh = *(__half2*)&gzu.x, gzh2 = *(__half2*)&gzu.y;
            __half2 gnh = *(__half2*)&gnu.x, gnh2 = *(__half2*)&gnu.y;
            float grv[4] = {__low2float(grh), __high2float(grh), __low2float(grh2), __high2float(grh2)};
            float gzv[4] = {__low2float(gzh), __high2float(gzh), __low2float(gzh2), __high2float(gzh2)};
            float gnv[4] = {__low2float(gnh), __high2float(gnh), __low2float(gnh2), __high2float(gnh2)};
            __half h16v[4];
            float hnew4[4];
            #pragma unroll
            for (int i = 0; i < 4; ++i) {
                int c = c0 + i;
                float ar = gh[gb * GH_STR + 0 * 16 + c];
                float az = gh[gb * GH_STR + 1 * 16 + c];
                float an = gh[gb * GH_STR + 2 * 16 + c];
                float rg = fast_sigmoid(grv[i] + ar + brt[i]);
                float zg = fast_sigmoid(gzv[i] + az + bzt[i]);
                float ng = fast_tanh(gnv[i] + bni[i] + rg * (an + bnh[i]));
                float hnew = (1.f - zg) * ng + zg * h_old[i];
                h_old[i] = hnew;               // exact fp32 state in registers
                hnew4[i] = hnew;
                h16v[i] = __float2half_rn(hnew);
            }
            size_t ho = (size_t)bglob * HID + gcol0;
            *(uint2*)(g_h16[nxt] + ho) = *(uint2*)h16v;
            if (s == STEPS - 1)
                *(float4*)(out + ho) = *(float4*)hnew4;
        }

        cntbar(bg0, 32u * (s + 2));
    }
}

// ---------------- launcher ----------------
extern "C" void kernel_launch(void* const* d_in, const int* in_sizes, int n_in,
                              void* d_out, int out_size) {
    const float* x   = (const float*)d_in[0];
    const float* wih = (const float*)d_in[1];
    const float* whh = (const float*)d_in[2];
    const float* bih = (const float*)d_in[3];
    const float* bhh = (const float*)d_in[4];
    float* out = (float*)d_out;

    cudaFuncSetAttribute(k_gru_recur, cudaFuncAttributeMaxDynamicSharedMemorySize,
                         REC2_SMEM);
    cudaFuncSetAttribute(k_gemm_gi, cudaFuncAttributeMaxDynamicSharedMemorySize,
                         GEMM_SMEM);

    k_w_convert<<<(GH * ISZ) / 1024, 256>>>(wih);
    k_x_transpose<<<dim3(STEPS / 32, ISZ / 32, BATCH), dim3(32, 8)>>>(x);
    k_gemm_gi<<<dim3(GH / 128, MROWS / 128), 256, GEMM_SMEM>>>();
    k_gru_recur<<<NCTA, 256, REC2_SMEM>>>(whh, bih, bhh, out);
}